// round 12
// baseline (speedup 1.0000x reference)
#include <cuda_runtime.h>
#include <cuda_fp16.h>
#include <cstdint>

// Problem constants
#define BB 128
#define TT 512
#define DD 512
#define HH 512
#define G4 2048            // 4*H
#define MX (BB*TT)

// Persistent-kernel tiling
#define NCTA 128
#define ROWS 32            // batch rows per CTA (one quarter)
#define NC   64            // permuted cols per CTA (=> 16 h cols)
#define AS2  260           // As stride in b32 units (256 + 4; %32==4 -> conflict-free)
#define BS2  260           // Bt stride in b32 units
#define ZST  68            // zs stride in floats

// Device scratch (allocation-free requirement: __device__ globals)
__device__ __half g_preh[(size_t)MX * G4];   // 256 MB: x@Wx + b (fp16), permuted cols
__device__ __half g_WxT[G4 * DD];            // permuted input weights, TRANSPOSED [col'][k], fp16
__device__ __half g_WhT[G4 * HH];            // permuted recurrent weights, TRANSPOSED [col'][k]
__device__ float  g_bp[G4];                  // permuted bias
__device__ __half g_hh[2][BB * HH];          // ping-pong hidden state (fp16, sorted order)
__device__ int    g_srcb[BB];                // sorted pos -> original batch row
__device__ int    g_nws[BB];                 // num_words, sorted descending
__device__ unsigned g_qcnt[4];               // per-quarter barrier counters

__device__ __forceinline__ uint32_t h2u(__half2 v) {
    return *reinterpret_cast<uint32_t*>(&v);
}

__device__ __forceinline__ void mma16h(float d[4], const uint32_t a[4], const uint32_t b[2]) {
    asm volatile(
        "mma.sync.aligned.m16n8k16.row.col.f32.f16.f16.f32 "
        "{%0,%1,%2,%3}, {%4,%5,%6,%7}, {%8,%9}, {%0,%1,%2,%3};"
        : "+f"(d[0]), "+f"(d[1]), "+f"(d[2]), "+f"(d[3])
        : "r"(a[0]), "r"(a[1]), "r"(a[2]), "r"(a[3]), "r"(b[0]), "r"(b[1]));
}

// ---------------------------------------------------------------------------
// Kernel 0: permute W (col' = 4*h + g) into fp16 transposed layouts, permute
// bias, AND (extra block 8192) sort batch rows by num_words descending.
// ---------------------------------------------------------------------------
__global__ void permute_W_kernel(const float* __restrict__ W, const float* __restrict__ bias,
                                 const int* __restrict__ nw) {
    if (blockIdx.x == 8192) {       // fused sort block
        int b = threadIdx.x;
        if (b < BB) {
            int my = nw[b];
            int rank = 0;
            for (int j = 0; j < BB; j++) {
                int v = nw[j];
                rank += (v > my) || (v == my && j < b);
            }
            g_srcb[rank] = b;
            g_nws[rank] = my;
        }
        return;
    }
    int idx = blockIdx.x * 256 + threadIdx.x;
    if (idx < 1024 * 2048) {
        int d = idx >> 11;
        int col = idx & 2047;
        int g = col >> 9;
        int h = col & 511;
        int colp = 4 * h + g;
        __half v = __float2half_rn(W[idx]);
        if (d < 512) g_WxT[(size_t)colp * 512 + d]         = v;
        else         g_WhT[(size_t)colp * 512 + (d - 512)] = v;
    }
    if (idx < 2048) {
        int g = idx >> 9;
        int h = idx & 511;
        g_bp[4 * h + g] = bias[idx];
    }
}

// ---------------------------------------------------------------------------
// Kernel 1: input projection GEMM  g_preh = fp16(X @ Wx + b), fp16 HMMA.
// RESTRUCTURED: one CTA per 128-row m-block; the A block (128x512 fp16,
// 128 KB) is staged in SMEM ONCE, then all 32 n-chunks are computed with
// B chunks (64x512 fp16, 64 KB) restaged from L2-resident WxT.
// X is read from DRAM exactly once (was 32x).
// ---------------------------------------------------------------------------
__global__ void __launch_bounds__(256) gemm_x_kernel(const float* __restrict__ X,
                                                     const int* __restrict__ nw) {
    const int m0 = blockIdx.x * 128;
    {
        int b = m0 >> 9;
        int t0 = m0 & 511;
        if (t0 >= nw[b]) return;          // whole block masked: g_preh never consumed
    }
    extern __shared__ unsigned char xsm[];
    uint32_t* As = (uint32_t*)xsm;                       // [128][AS2] b32 (fp16x2)
    uint32_t* Bs = (uint32_t*)(xsm + 128 * AS2 * 4);     // [64][BS2] b32 (B^T rows)

    const int tid = threadIdx.x;
    const int lane = tid & 31;
    const int warp = tid >> 5;
    const int wm = warp >> 1, wn = warp & 1;
    const int ln4 = lane >> 2;
    const int kl  = lane & 3;

    // --- stage full A block once: 128 rows x 512 k, fp32 -> fp16 ---
    {
        int row  = tid >> 1;
        int half = tid & 1;
        const float* src = X + (size_t)(m0 + row) * 512 + half * 256;
        uint32_t* dst = As + row * AS2 + half * 128;
        #pragma unroll 8
        for (int j = 0; j < 64; j++) {
            float4 v = *(const float4*)(src + 4 * j);
            uint2 p = make_uint2(h2u(__floats2half2_rn(v.x, v.y)),
                                 h2u(__floats2half2_rn(v.z, v.w)));
            *(uint2*)(dst + 2 * j) = p;
        }
    }
    __syncthreads();

    // --- loop over 32 n-chunks of 64 cols' ---
    for (int cn = 0; cn < 32; cn++) {
        const int n0 = cn * 64;
        if (cn) __syncthreads();          // protect Bs reuse

        // B stage: 64 rows x 512 k fp16, straight copy from WxT (L2-hot)
        {
            int n   = tid >> 2;
            int seg = tid & 3;
            const uint4* src = (const uint4*)(g_WxT + (size_t)(n0 + n) * 512 + seg * 128);
            uint32_t* dst = Bs + n * BS2 + seg * 64;
            #pragma unroll
            for (int i = 0; i < 16; i++) {
                uint4 v = src[i];
                *(uint4*)(dst + i * 4) = v;
            }
        }
        __syncthreads();

        // MMA: 8 warps = 4 m-tiles x 2 n-tiles, warp tile 32x32, K=512
        float acc[2][4][4];
        #pragma unroll
        for (int s = 0; s < 2; s++)
            #pragma unroll
            for (int u = 0; u < 4; u++)
                #pragma unroll
                for (int i = 0; i < 4; i++) acc[s][u][i] = 0.f;

        #pragma unroll 8
        for (int ks = 0; ks < 32; ks++) {
            const int kb = ks * 8 + kl;
            uint32_t a[2][4], bb[4][2];
            #pragma unroll
            for (int s = 0; s < 2; s++) {
                int rr = wm * 32 + s * 16 + ln4;
                a[s][0] = As[rr * AS2 + kb];
                a[s][1] = As[(rr + 8) * AS2 + kb];
                a[s][2] = As[rr * AS2 + kb + 4];
                a[s][3] = As[(rr + 8) * AS2 + kb + 4];
            }
            #pragma unroll
            for (int u = 0; u < 4; u++) {
                int cc = wn * 32 + u * 8 + ln4;
                bb[u][0] = Bs[cc * BS2 + kb];
                bb[u][1] = Bs[cc * BS2 + kb + 4];
            }
            #pragma unroll
            for (int s = 0; s < 2; s++)
                #pragma unroll
                for (int u = 0; u < 4; u++)
                    mma16h(acc[s][u], a[s], bb[u]);
        }

        // write-out: fp16 pre-activations + bias
        #pragma unroll
        for (int s = 0; s < 2; s++) {
            int row = m0 + wm * 32 + s * 16 + ln4;
            #pragma unroll
            for (int u = 0; u < 4; u++) {
                int col = n0 + wn * 32 + u * 8 + 2 * kl;
                float b0 = g_bp[col], b1 = g_bp[col + 1];
                size_t base = (size_t)row * 2048 + col;
                *(__half2*)(g_preh + base) =
                    __floats2half2_rn(acc[s][u][0] + b0, acc[s][u][1] + b1);
                *(__half2*)(g_preh + base + (size_t)8 * 2048) =
                    __floats2half2_rn(acc[s][u][2] + b0, acc[s][u][3] + b1);
            }
        }
    }
}

// ---------------------------------------------------------------------------
// Kernel 2: init — reset counters, publish fp16 initial h (sorted order).
// ---------------------------------------------------------------------------
__global__ void init_state_kernel(const float* __restrict__ ih) {
    int i = blockIdx.x * 256 + threadIdx.x;
    if (i < 4) g_qcnt[i] = 0u;
    if (i < BB * HH) {
        int srow = i >> 9;
        int col = i & 511;
        int borig = g_srcb[srow];
        g_hh[0][i] = __float2half_rn(ih[borig * HH + col]);
    }
}

// ---------------------------------------------------------------------------
// Kernel 3: persistent LSTM recurrence, fp16 HMMA (m16n8k16, fp32 accum).
// 128 CTAs = 4 sorted batch quarters x 32 col' chunks of 64.
// Wh MMA fragments permanently in registers; h refill via cp.async.
// (UNCHANGED from R11 — protecting the win.)
// ---------------------------------------------------------------------------
__global__ void __launch_bounds__(256, 1) lstm_persist_kernel(
    const float* __restrict__ ic, const float* __restrict__ ih,
    float* __restrict__ out, float* __restrict__ c_final, float* __restrict__ h_final)
{
    extern __shared__ unsigned char smraw[];
    uint32_t* As32 = (uint32_t*)smraw;                                   // [32][AS2] b32 (fp16x2)
    uint32_t* Bt32 = (uint32_t*)(smraw + ROWS * AS2 * 4);                // [64][BS2] b32 (B^T)
    float*    zs   = (float*)(smraw + ROWS * AS2 * 4 + NC * BS2 * 4);    // [4][32][ZST]

    uint32_t as_base;
    asm("{ .reg .u64 t; cvta.to.shared.u64 t, %1; cvt.u32.u64 %0, t; }"
        : "=r"(as_base) : "l"(As32));

    const int tid  = threadIdx.x;
    const int lane = tid & 31;
    const int warp = tid >> 5;
    const int rb = blockIdx.x & 3;        // batch quarter (sorted order)
    const int cn = blockIdx.x >> 2;       // 0..31 col' chunk
    const int n0 = cn * NC;               // col' base

    // --- one-time: load Wh^T slice into SMEM (fp16 pairs along k) ---
    {
        int cc  = tid >> 2;               // 0..63
        int seg = tid & 3;                // quarter of the 512-k row
        const uint4* src = (const uint4*)(g_WhT + (size_t)(n0 + cc) * 512 + seg * 128);
        uint32_t* dst = Bt32 + cc * BS2 + seg * 64;
        #pragma unroll
        for (int i = 0; i < 16; i++) {
            uint4 v = src[i];
            *(uint4*)(dst + i * 4) = v;
        }
    }

    // --- epilogue mapping: thread owns (srow, hc0) and (srow, hc0+1) ---
    const int r_ep = tid & 31;                 // local batch row
    const int hl2  = (tid >> 5) * 2;           // local h col pair (0,2,..,14)
    const int srow = rb * ROWS + r_ep;         // sorted batch row
    const int borig = g_srcb[srow];            // original batch row
    const int mynw  = g_nws[srow];
    const int qmax  = g_nws[rb * ROWS];        // max num_words in this quarter
    float c0  = ic[borig * HH + cn * 16 + hl2];
    float c1  = ic[borig * HH + cn * 16 + hl2 + 1];
    float hr0 = ih[borig * HH + cn * 16 + hl2];
    float hr1 = ih[borig * HH + cn * 16 + hl2 + 1];
    const size_t outcol = (size_t)borig * HH + cn * 16 + hl2;

    // --- MMA mapping: 8 warps = 2 n-halves x 4 K-slices; warp tile 32x32 ---
    const int wn = warp & 1;
    const int kw = warp >> 1;
    const int kwb = kw * 64;                   // K-slice base in b32 units
    const int ln4 = lane >> 2;
    const int kl  = lane & 3;

    // --- A-fill mapping: 32 rows x 64 uint4 (8 halves each) ---
    const int fr = tid >> 3;                   // row 0..31
    const int fc = tid & 7;                    // uint4 group

    unsigned* const qcnt = &g_qcnt[rb];

    __syncthreads();                           // Bt ready

    // --- load Wh fragments into registers ONCE (static across all steps) ---
    uint32_t breg[8][4][2];
    #pragma unroll
    for (int ks = 0; ks < 8; ks++) {
        const int kb = kwb + ks * 8 + kl;
        #pragma unroll
        for (int u = 0; u < 4; u++) {
            int cc = wn * 32 + u * 8 + ln4;
            breg[ks][u][0] = Bt32[cc * BS2 + kb];
            breg[ks][u][1] = Bt32[cc * BS2 + kb + 4];
        }
    }

    // prefetch pre-activations for step 0 (8 fp16 gate values)
    uint4 praw = make_uint4(0, 0, 0, 0);
    if (qmax > 0)
        praw = __ldcs((const uint4*)(g_preh + ((size_t)borig * TT) * 2048 + n0 + hl2 * 4));

    for (int t = 0; t < qmax; t++) {
        const __half* __restrict__ h_in  = g_hh[t & 1];
        __half*       __restrict__ h_out = g_hh[(t & 1) ^ 1];

        // fill As with this quarter's 32 h rows via cp.async (L1-bypass .cg)
        {
            const __half* src = h_in + (size_t)(rb * ROWS + fr) * HH + fc * 8;
            uint32_t dstb = as_base + (uint32_t)(fr * AS2 + fc * 4) * 4u;
            #pragma unroll
            for (int j = 0; j < 8; j++) {
                asm volatile("cp.async.cg.shared.global [%0], [%1], 16;"
                             :: "r"(dstb + (uint32_t)(j * 32 * 4)),
                                "l"(src + j * 64) : "memory");
            }
            asm volatile("cp.async.commit_group;" ::: "memory");
            asm volatile("cp.async.wait_group 0;" ::: "memory");
        }
        __syncthreads();

        // GEMM: [32 x 128] @ [128 x 32] per warp (K-slice kw, n-half wn)
        float acc[2][4][4];
        #pragma unroll
        for (int s = 0; s < 2; s++)
            #pragma unroll
            for (int u = 0; u < 4; u++)
                #pragma unroll
                for (int i = 0; i < 4; i++) acc[s][u][i] = 0.f;

        #pragma unroll
        for (int ks = 0; ks < 8; ks++) {
            const int kb = kwb + ks * 8 + kl;
            uint32_t a[2][4];
            #pragma unroll
            for (int s = 0; s < 2; s++) {
                int rr = s * 16 + ln4;
                a[s][0] = As32[rr * AS2 + kb];
                a[s][1] = As32[(rr + 8) * AS2 + kb];
                a[s][2] = As32[rr * AS2 + kb + 4];
                a[s][3] = As32[(rr + 8) * AS2 + kb + 4];
            }
            #pragma unroll
            for (int s = 0; s < 2; s++)
                #pragma unroll
                for (int u = 0; u < 4; u++)
                    mma16h(acc[s][u], a[s], breg[ks][u]);
        }

        // store partials: zs[kw][row][col]
        {
            int zcb = wn * 32 + 2 * kl;
            #pragma unroll
            for (int s = 0; s < 2; s++) {
                int row = s * 16 + ln4;
                #pragma unroll
                for (int u = 0; u < 4; u++) {
                    int col = zcb + u * 8;
                    *(float2*)&zs[(kw * 32 + row) * ZST + col]     =
                        make_float2(acc[s][u][0], acc[s][u][1]);
                    *(float2*)&zs[(kw * 32 + row + 8) * ZST + col] =
                        make_float2(acc[s][u][2], acc[s][u][3]);
                }
            }
        }
        __syncthreads();

        // reduce 4 K-partials + fused gate epilogue (2 owned h cols)
        float4 z0 = make_float4(0.f, 0.f, 0.f, 0.f);
        float4 z1 = make_float4(0.f, 0.f, 0.f, 0.f);
        #pragma unroll
        for (int s = 0; s < 4; s++) {
            const float* zp = zs + ((s * 32 + r_ep) * ZST + hl2 * 4);
            float4 a0 = *(const float4*)zp;
            float4 a1 = *(const float4*)(zp + 4);
            z0.x += a0.x; z0.y += a0.y; z0.z += a0.z; z0.w += a0.w;
            z1.x += a1.x; z1.y += a1.y; z1.z += a1.z; z1.w += a1.w;
        }

        const __half2* ph = (const __half2*)&praw;
        float2 q0 = __half22float2(ph[0]);
        float2 q1 = __half22float2(ph[1]);
        float2 q2 = __half22float2(ph[2]);
        float2 q3 = __half22float2(ph[3]);

        float zi0 = z0.x + q0.x, zj0 = z0.y + q0.y, zf0 = z0.z + q1.x, zo0 = z0.w + q1.y;
        float zi1 = z1.x + q2.x, zj1 = z1.y + q2.y, zf1 = z1.z + q3.x, zo1 = z1.w + q3.y;

        float si0 = 1.f / (1.f + __expf(-zi0));
        float sf0 = 1.f / (1.f + __expf(-(zf0 + 1.0f)));
        float so0 = 1.f / (1.f + __expf(-zo0));
        float tj0 = tanhf(zj0);
        float nc0 = c0 * sf0 + si0 * tj0;
        float nh0 = tanhf(nc0) * so0;

        float si1 = 1.f / (1.f + __expf(-zi1));
        float sf1 = 1.f / (1.f + __expf(-(zf1 + 1.0f)));
        float so1 = 1.f / (1.f + __expf(-zo1));
        float tj1 = tanhf(zj1);
        float nc1 = c1 * sf1 + si1 * tj1;
        float nh1 = tanhf(nc1) * so1;

        bool m = t < mynw;
        c0 = m ? nc0 : c0;   c1 = m ? nc1 : c1;
        hr0 = m ? nh0 : hr0; hr1 = m ? nh1 : hr1;

        size_t sidx = (size_t)srow * HH + cn * 16 + hl2;
        *(__half2*)(h_out + sidx) = __floats2half2_rn(hr0, hr1);
        __stcs((float2*)&out[(size_t)t * (BB * HH) + outcol],
               make_float2(m ? nh0 : 0.f, m ? nh1 : 0.f));

        // quarter-local barrier — only while a next step will consume h
        if (t + 1 < qmax) {
            praw = __ldcs((const uint4*)(g_preh +
                       ((size_t)borig * TT + (t + 1)) * 2048 + n0 + hl2 * 4));

            __syncthreads();                       // all h_out stores issued CTA-wide
            if (tid == 0) {
                asm volatile("red.release.gpu.add.u32 [%0], %1;"
                             :: "l"(qcnt), "r"(1u) : "memory");
                unsigned target = 32u * (unsigned)(t + 1);
                unsigned v;
                do {
                    asm volatile("ld.acquire.gpu.u32 %0, [%1];"
                                 : "=r"(v) : "l"(qcnt) : "memory");
                } while (v < target);
            }
            __syncthreads();                       // acquire propagates CTA-wide
        }
    }

    // bulk zeros for the inactive tail (off the critical path)
    for (int t = qmax; t < TT; t++)
        __stcs((float2*)&out[(size_t)t * (BB * HH) + outcol], make_float2(0.f, 0.f));

    // final states (each (b,h) pair owned by exactly one thread)
    *(float2*)&c_final[outcol] = make_float2(c0, c1);
    *(float2*)&h_final[outcol] = make_float2(hr0, hr1);
}

// ---------------------------------------------------------------------------
extern "C" void kernel_launch(void* const* d_in, const int* in_sizes, int n_in,
                              void* d_out, int out_size) {
    const float* x    = (const float*)d_in[0];  // [B,T,D]
    const int*   nw   = (const int*)  d_in[1];  // [B]
    const float* ic   = (const float*)d_in[2];  // [B,H]
    const float* ih   = (const float*)d_in[3];  // [B,H]
    const float* W    = (const float*)d_in[4];  // [D+H, 4H]
    const float* bias = (const float*)d_in[5];  // [4H]

    float* out     = (float*)d_out;
    float* c_final = out + (size_t)TT * BB * HH;
    float* h_final = c_final + (size_t)BB * HH;

    const int smem_bytes = ROWS * AS2 * 4 + NC * BS2 * 4 + 4 * ROWS * ZST * 4; // 134656
    cudaFuncSetAttribute(lstm_persist_kernel,
                         cudaFuncAttributeMaxDynamicSharedMemorySize, smem_bytes);

    const int xsmem_bytes = (128 * AS2 + 64 * BS2) * 4;                        // 199680
    cudaFuncSetAttribute(gemm_x_kernel,
                         cudaFuncAttributeMaxDynamicSharedMemorySize, xsmem_bytes);

    permute_W_kernel<<<8193, 256>>>(W, bias, nw);       // includes fused sort block
    gemm_x_kernel<<<512, 256, xsmem_bytes>>>(x, nw);
    init_state_kernel<<<(BB * HH + 255) / 256, 256>>>(ih);
    lstm_persist_kernel<<<NCTA, 256, smem_bytes>>>(ic, ih, out, c_final, h_final);
}